// round 1
// baseline (speedup 1.0000x reference)
#include <cuda_runtime.h>

#define T_LEN  4096
#define DH     64
#define NF     256
#define NHEADS 64          // B*H
#define CHUNK  512
#define SUB    64
#define SPLITS 8           // T_LEN / CHUNK
#define DS     0.35355339059327373f   // 64^-0.25

// Scratch (allocation-free rule: __device__ globals)
__device__ float g_ctx[NHEADS * NF * DH];   // per-head context [NF][DH]
__device__ float g_ksum[NHEADS * NF];       // per-head ksum    [NF]

// Fast exp for x <= 0: exp(x) = 2^(x*log2e), poly on [-0.5,0.5] + exponent bit trick.
// ~7 fma/alu ops, rel err ~2e-6. Avoids the MUFU EX2 throughput wall.
__device__ __forceinline__ float fexp(float x) {
    x = fmaxf(x, -80.0f);
    float t = x * 1.4426950408889634f;
    float r = t + 12582912.0f;                 // round-to-nearest-int via magic
    int   e = __float_as_int(r) << 23;         // == n << 23 (magic low 9 bits are 0)
    r -= 12582912.0f;
    float f = t - r;                           // f in [-0.5, 0.5]
    float p = 1.3333558e-3f;
    p = fmaf(p, f, 9.6181291e-3f);
    p = fmaf(p, f, 5.5504109e-2f);
    p = fmaf(p, f, 2.4022651e-1f);
    p = fmaf(p, f, 6.9314718e-1f);
    p = fmaf(p, f, 1.0f);
    return __int_as_float(__float_as_int(p) + e);
}

__global__ void zero_scratch() {
    const int n1 = NHEADS * NF * DH;
    const int n2 = NHEADS * NF;
    for (int i = blockIdx.x * blockDim.x + threadIdx.x; i < n1; i += gridDim.x * blockDim.x)
        g_ctx[i] = 0.0f;
    for (int i = blockIdx.x * blockDim.x + threadIdx.x; i < n2; i += gridDim.x * blockDim.x)
        g_ksum[i] = 0.0f;
}

// ---------------------------------------------------------------------------
// Phase 1: keys -> context[NF][DH], ksum[NF] per head.
// Grid (NHEADS, SPLITS), 256 threads. Each CTA: 512 key tokens in 64-token subtiles.
// ---------------------------------------------------------------------------
__global__ __launch_bounds__(256, 1) void phase1_kernel(
    const float* __restrict__ Kg, const float* __restrict__ Vg, const float* __restrict__ Pg)
{
    extern __shared__ float sm[];
    float* sProjT = sm;                      // [DH][NF]  16384 f
    float* sK     = sProjT + DH * NF;        // [SUB][DH]  4096 f (pre-scaled by DS)
    float* sV     = sK + SUB * DH;           // [SUB][DH]  4096 f
    float* sPhi   = sV + SUB * DH;           // [SUB][NF] 16384 f
    float* sDn    = sPhi + SUB * NF;         // [SUB]

    const int head  = blockIdx.x;
    const int split = blockIdx.y;
    const int tid   = threadIdx.x;
    const int tn = tid >> 5, tj = tid & 31;  // GEMM1: 8 token-rows x 8 feats per thread
    const int jb = tid >> 3, eb = tid & 7;   // GEMM2: 8 feats x 8 e per thread

    // Load projection transposed: sProjT[d][j] = P[j*DH + d]
    {
        const float4* P4 = (const float4*)Pg;
        for (int i4 = tid; i4 < NF * DH / 4; i4 += 256) {
            float4 a = P4[i4];
            int j = i4 >> 4;
            int d = (i4 & 15) << 2;
            sProjT[(d + 0) * NF + j] = a.x;
            sProjT[(d + 1) * NF + j] = a.y;
            sProjT[(d + 2) * NF + j] = a.z;
            sProjT[(d + 3) * NF + j] = a.w;
        }
    }

    float ctx[8][8];
    #pragma unroll
    for (int i = 0; i < 8; ++i)
        #pragma unroll
        for (int j = 0; j < 8; ++j) ctx[i][j] = 0.0f;
    float ks[8];
    #pragma unroll
    for (int j = 0; j < 8; ++j) ks[j] = 0.0f;

    const float* Kbase = Kg + ((size_t)head * T_LEN + (size_t)split * CHUNK) * DH;
    const float* Vbase = Vg + ((size_t)head * T_LEN + (size_t)split * CHUNK) * DH;

    for (int sub = 0; sub < CHUNK / SUB; ++sub) {
        __syncthreads();   // prior GEMM2 done with sPhi/sV; prior epilogue done with sDn
        {
            const float4* kp4 = (const float4*)(Kbase + sub * SUB * DH);
            const float4* vp4 = (const float4*)(Vbase + sub * SUB * DH);
            #pragma unroll
            for (int c = 0; c < 4; ++c) {
                int i4 = tid + c * 256;
                float4 a = kp4[i4];
                a.x *= DS; a.y *= DS; a.z *= DS; a.w *= DS;
                ((float4*)sK)[i4] = a;
                ((float4*)sV)[i4] = vp4[i4];
            }
        }
        __syncthreads();
        if (tid < SUB) {   // dn = 0.5 * sum(scaled_k^2)
            const float4* r = (const float4*)(sK + tid * DH);
            float s = 0.0f;
            #pragma unroll
            for (int c = 0; c < 16; ++c) {
                float4 a = r[c];
                s = fmaf(a.x, a.x, s); s = fmaf(a.y, a.y, s);
                s = fmaf(a.z, a.z, s); s = fmaf(a.w, a.w, s);
            }
            sDn[tid] = 0.5f * s;
        }
        // GEMM1: acc[i][j] = sum_d sK[n][d] * projT[d][j]
        float acc[8][8];
        #pragma unroll
        for (int i = 0; i < 8; ++i)
            #pragma unroll
            for (int j = 0; j < 8; ++j) acc[i][j] = 0.0f;
        #pragma unroll 4
        for (int d = 0; d < DH; ++d) {
            float4 b0 = *(const float4*)&sProjT[d * NF + tj * 8];
            float4 b1 = *(const float4*)&sProjT[d * NF + tj * 8 + 4];
            float b[8] = {b0.x, b0.y, b0.z, b0.w, b1.x, b1.y, b1.z, b1.w};
            #pragma unroll
            for (int i = 0; i < 8; ++i) {
                float a = sK[(tn * 8 + i) * DH + d];
                #pragma unroll
                for (int j = 0; j < 8; ++j) acc[i][j] = fmaf(a, b[j], acc[i][j]);
            }
        }
        __syncthreads();   // sDn ready
        // Epilogue: rowmax (warp covers full NF for its 8 tokens), exp, store Phi
        #pragma unroll
        for (int i = 0; i < 8; ++i) {
            float m = acc[i][0];
            #pragma unroll
            for (int j = 1; j < 8; ++j) m = fmaxf(m, acc[i][j]);
            #pragma unroll
            for (int s = 16; s > 0; s >>= 1)
                m = fmaxf(m, __shfl_xor_sync(0xffffffffu, m, s));
            float off = sDn[tn * 8 + i] + m;
            float4 o0, o1;
            o0.x = fexp(acc[i][0] - off); o0.y = fexp(acc[i][1] - off);
            o0.z = fexp(acc[i][2] - off); o0.w = fexp(acc[i][3] - off);
            o1.x = fexp(acc[i][4] - off); o1.y = fexp(acc[i][5] - off);
            o1.z = fexp(acc[i][6] - off); o1.w = fexp(acc[i][7] - off);
            *(float4*)&sPhi[(tn * 8 + i) * NF + tj * 8]     = o0;
            *(float4*)&sPhi[(tn * 8 + i) * NF + tj * 8 + 4] = o1;
        }
        __syncthreads();
        // GEMM2: ctx[j][e] += Phi[n][j] * V[n][e]; ksum via eb==0 lanes
        #pragma unroll 2
        for (int n = 0; n < SUB; ++n) {
            float4 p0 = *(const float4*)&sPhi[n * NF + jb * 8];
            float4 p1 = *(const float4*)&sPhi[n * NF + jb * 8 + 4];
            float4 v0 = *(const float4*)&sV[n * DH + eb * 8];
            float4 v1 = *(const float4*)&sV[n * DH + eb * 8 + 4];
            float pp[8] = {p0.x, p0.y, p0.z, p0.w, p1.x, p1.y, p1.z, p1.w};
            float vv[8] = {v0.x, v0.y, v0.z, v0.w, v1.x, v1.y, v1.z, v1.w};
            #pragma unroll
            for (int jj = 0; jj < 8; ++jj)
                #pragma unroll
                for (int ee = 0; ee < 8; ++ee)
                    ctx[jj][ee] = fmaf(pp[jj], vv[ee], ctx[jj][ee]);
            if (eb == 0) {
                #pragma unroll
                for (int jj = 0; jj < 8; ++jj) ks[jj] += pp[jj];
            }
        }
    }
    float* cd = g_ctx + head * NF * DH;
    #pragma unroll
    for (int jj = 0; jj < 8; ++jj)
        #pragma unroll
        for (int ee = 0; ee < 8; ++ee)
            atomicAdd(&cd[(jb * 8 + jj) * DH + eb * 8 + ee], ctx[jj][ee]);
    if (eb == 0) {
        float* kd = g_ksum + head * NF;
        #pragma unroll
        for (int jj = 0; jj < 8; ++jj) atomicAdd(&kd[jb * 8 + jj], ks[jj]);
    }
}

// ---------------------------------------------------------------------------
// Phase 2: queries -> out = (Psi @ ctx) / (Psi . ksum)
// Grid (NHEADS, SPLITS), 256 threads.
// ---------------------------------------------------------------------------
__global__ __launch_bounds__(256, 1) void phase2_kernel(
    const float* __restrict__ Qg, const float* __restrict__ Pg, float* __restrict__ Og)
{
    extern __shared__ float sm[];
    float* sProjT = sm;                      // [DH][NF]
    float* sCtx   = sProjT + DH * NF;        // [NF][DH]
    float* sQ     = sCtx + NF * DH;          // [SUB][DH]
    float* sPsi   = sQ + SUB * DH;           // [SUB][NF]
    float* sKsum  = sPsi + SUB * NF;         // [NF]
    float* sDen   = sKsum + NF;              // [SUB]

    const int head = blockIdx.x, split = blockIdx.y, tid = threadIdx.x;
    const int tn = tid >> 5, tj = tid & 31;   // GEMM1 coords
    const int nb = tid >> 4, ebq = tid & 15;  // GEMM2 coords: 4 tokens x 4 e

    {
        const float4* P4 = (const float4*)Pg;
        for (int i4 = tid; i4 < NF * DH / 4; i4 += 256) {
            float4 a = P4[i4];
            int j = i4 >> 4;
            int d = (i4 & 15) << 2;
            sProjT[(d + 0) * NF + j] = a.x;
            sProjT[(d + 1) * NF + j] = a.y;
            sProjT[(d + 2) * NF + j] = a.z;
            sProjT[(d + 3) * NF + j] = a.w;
        }
        const float4* C4 = (const float4*)(g_ctx + head * NF * DH);
        #pragma unroll
        for (int c = 0; c < 16; ++c)
            ((float4*)sCtx)[tid + c * 256] = C4[tid + c * 256];
        if (tid < NF) sKsum[tid] = g_ksum[head * NF + tid];
    }
    __syncthreads();
    float ksw[8];
    {
        float4 k0 = *(const float4*)&sKsum[tj * 8];
        float4 k1 = *(const float4*)&sKsum[tj * 8 + 4];
        ksw[0] = k0.x; ksw[1] = k0.y; ksw[2] = k0.z; ksw[3] = k0.w;
        ksw[4] = k1.x; ksw[5] = k1.y; ksw[6] = k1.z; ksw[7] = k1.w;
    }

    const float* Qbase = Qg + ((size_t)head * T_LEN + (size_t)split * CHUNK) * DH;
    float*       Obase = Og + ((size_t)head * T_LEN + (size_t)split * CHUNK) * DH;

    for (int sub = 0; sub < CHUNK / SUB; ++sub) {
        __syncthreads();
        {
            const float4* qp4 = (const float4*)(Qbase + sub * SUB * DH);
            #pragma unroll
            for (int c = 0; c < 4; ++c) {
                int i4 = tid + c * 256;
                float4 a = qp4[i4];
                a.x *= DS; a.y *= DS; a.z *= DS; a.w *= DS;
                ((float4*)sQ)[i4] = a;
            }
        }
        __syncthreads();
        float acc[8][8];
        #pragma unroll
        for (int i = 0; i < 8; ++i)
            #pragma unroll
            for (int j = 0; j < 8; ++j) acc[i][j] = 0.0f;
        #pragma unroll 4
        for (int d = 0; d < DH; ++d) {
            float4 b0 = *(const float4*)&sProjT[d * NF + tj * 8];
            float4 b1 = *(const float4*)&sProjT[d * NF + tj * 8 + 4];
            float b[8] = {b0.x, b0.y, b0.z, b0.w, b1.x, b1.y, b1.z, b1.w};
            #pragma unroll
            for (int i = 0; i < 8; ++i) {
                float a = sQ[(tn * 8 + i) * DH + d];
                #pragma unroll
                for (int j = 0; j < 8; ++j) acc[i][j] = fmaf(a, b[j], acc[i][j]);
            }
        }
        // Epilogue: rowmax, psi=exp(dp-m), denom = psi . ksum (warp allreduce)
        #pragma unroll
        for (int i = 0; i < 8; ++i) {
            float m = acc[i][0];
            #pragma unroll
            for (int j = 1; j < 8; ++j) m = fmaxf(m, acc[i][j]);
            #pragma unroll
            for (int s = 16; s > 0; s >>= 1)
                m = fmaxf(m, __shfl_xor_sync(0xffffffffu, m, s));
            float4 o0, o1;
            o0.x = fexp(acc[i][0] - m); o0.y = fexp(acc[i][1] - m);
            o0.z = fexp(acc[i][2] - m); o0.w = fexp(acc[i][3] - m);
            o1.x = fexp(acc[i][4] - m); o1.y = fexp(acc[i][5] - m);
            o1.z = fexp(acc[i][6] - m); o1.w = fexp(acc[i][7] - m);
            float ds = o0.x * ksw[0];
            ds = fmaf(o0.y, ksw[1], ds); ds = fmaf(o0.z, ksw[2], ds);
            ds = fmaf(o0.w, ksw[3], ds); ds = fmaf(o1.x, ksw[4], ds);
            ds = fmaf(o1.y, ksw[5], ds); ds = fmaf(o1.z, ksw[6], ds);
            ds = fmaf(o1.w, ksw[7], ds);
            #pragma unroll
            for (int s = 16; s > 0; s >>= 1)
                ds += __shfl_xor_sync(0xffffffffu, ds, s);
            if (tj == 0) sDen[tn * 8 + i] = ds;
            *(float4*)&sPsi[(tn * 8 + i) * NF + tj * 8]     = o0;
            *(float4*)&sPsi[(tn * 8 + i) * NF + tj * 8 + 4] = o1;
        }
        __syncthreads();
        // GEMM2: out[n][e] = sum_j Psi[n][j] * ctx[j][e]
        float o4[4][4];
        #pragma unroll
        for (int i = 0; i < 4; ++i)
            #pragma unroll
            for (int e = 0; e < 4; ++e) o4[i][e] = 0.0f;
        #pragma unroll 4
        for (int j = 0; j < NF; ++j) {
            float4 c = *(const float4*)&sCtx[j * DH + ebq * 4];
            #pragma unroll
            for (int i = 0; i < 4; ++i) {
                float p = sPsi[(nb * 4 + i) * NF + j];
                o4[i][0] = fmaf(p, c.x, o4[i][0]);
                o4[i][1] = fmaf(p, c.y, o4[i][1]);
                o4[i][2] = fmaf(p, c.z, o4[i][2]);
                o4[i][3] = fmaf(p, c.w, o4[i][3]);
            }
        }
        #pragma unroll
        for (int i = 0; i < 4; ++i) {
            float inv = 1.0f / sDen[nb * 4 + i];
            float4 w;
            w.x = o4[i][0] * inv; w.y = o4[i][1] * inv;
            w.z = o4[i][2] * inv; w.w = o4[i][3] * inv;
            *(float4*)&Obase[(size_t)(sub * SUB + nb * 4 + i) * DH + ebq * 4] = w;
        }
    }
}

extern "C" void kernel_launch(void* const* d_in, const int* in_sizes, int n_in,
                              void* d_out, int out_size) {
    const float* q    = (const float*)d_in[0];
    const float* k    = (const float*)d_in[1];
    const float* v    = (const float*)d_in[2];
    const float* proj = (const float*)d_in[3];
    float* out = (float*)d_out;

    const int smem1 = (DH * NF + SUB * DH + SUB * DH + SUB * NF + SUB) * 4;               // 164096 B
    const int smem2 = (DH * NF + NF * DH + SUB * DH + SUB * NF + NF + SUB) * 4;           // 214272 B
    cudaFuncSetAttribute(phase1_kernel, cudaFuncAttributeMaxDynamicSharedMemorySize, smem1);
    cudaFuncSetAttribute(phase2_kernel, cudaFuncAttributeMaxDynamicSharedMemorySize, smem2);

    zero_scratch<<<512, 256>>>();
    phase1_kernel<<<dim3(NHEADS, SPLITS), 256, smem1>>>(k, v, proj);
    phase2_kernel<<<dim3(NHEADS, SPLITS), 256, smem2>>>(q, proj, out);
}

// round 4
// speedup vs baseline: 2.1484x; 2.1484x over previous
#include <cuda_runtime.h>
#include <cuda_bf16.h>
#include <cstdint>

#define T_LEN   4096
#define DH      64
#define NF      256
#define NHEADS  64
#define TS      128
#define SPLITS  8
#define TILES   4
#define DS      0.35355339059327373f   // 64^-0.25

// ctx scratch, transposed: [head][e 0..63, ksum=64][j 0..255]
__device__ float g_ctxT[NHEADS * 65 * NF];

// ---------------------------------------------------------------------------
// helpers
// ---------------------------------------------------------------------------
__device__ __forceinline__ uint32_t pack2(float lo, float hi) {
    uint32_t r;
    asm("cvt.rn.satfinite.bf16x2.f32 %0, %1, %2;" : "=r"(r) : "f"(hi), "f"(lo));
    return r;
}
// split (x0,x1) into bf16 hi pair + bf16 lo (residual) pair
__device__ __forceinline__ void split2(float x0, float x1, uint32_t& h, uint32_t& l) {
    h = pack2(x0, x1);
    float h0 = __uint_as_float(h << 16);
    float h1 = __uint_as_float(h & 0xFFFF0000u);
    l = pack2(x0 - h0, x1 - h1);
}
__device__ __forceinline__ void mma16816(float* c, const uint32_t* a, uint32_t b0, uint32_t b1) {
    asm volatile(
        "mma.sync.aligned.m16n8k16.row.col.f32.bf16.bf16.f32 "
        "{%0,%1,%2,%3}, {%4,%5,%6,%7}, {%8,%9}, {%0,%1,%2,%3};"
        : "+f"(c[0]), "+f"(c[1]), "+f"(c[2]), "+f"(c[3])
        : "r"(a[0]), "r"(a[1]), "r"(a[2]), "r"(a[3]), "r"(b0), "r"(b1));
}
// 3-term split mma: (aH+aL)(bH+bL) ~= aH*bH + aH*bL + aL*bH
__device__ __forceinline__ void mma3(float* c, const uint32_t* aH, const uint32_t* aL,
                                     uint32_t bh0, uint32_t bh1, uint32_t bl0, uint32_t bl1) {
    mma16816(c, aH, bh0, bh1);
    mma16816(c, aH, bl0, bl1);
    mma16816(c, aL, bh0, bh1);
}

// fast exp, ~7 FMA, rel err ~2e-6
__device__ __forceinline__ float fexp(float x) {
    x = fmaxf(x, -80.0f);
    float t = x * 1.4426950408889634f;
    float r = t + 12582912.0f;
    int   e = __float_as_int(r) << 23;
    r -= 12582912.0f;
    float f = t - r;
    float p = 1.3333558e-3f;
    p = fmaf(p, f, 9.6181291e-3f);
    p = fmaf(p, f, 5.5504109e-2f);
    p = fmaf(p, f, 2.4022651e-1f);
    p = fmaf(p, f, 6.9314718e-1f);
    p = fmaf(p, f, 1.0f);
    return __int_as_float(__float_as_int(p) + e);
}

__global__ void zero_scratch() {
    const int n = NHEADS * 65 * NF;
    for (int i = blockIdx.x * blockDim.x + threadIdx.x; i < n; i += gridDim.x * blockDim.x)
        g_ctxT[i] = 0.0f;
}

// proj staging (both phases): row j per thread, stride 144 B (64 halves + 8 pad)
__device__ __forceinline__ void stage_proj(char* pHi, char* pLo, const float* P, int tid) {
    int j = tid;
    const float2* pr = (const float2*)(P + j * 64);
    #pragma unroll
    for (int kp = 0; kp < 32; ++kp) {
        float2 a = pr[kp];
        uint32_t h, l;
        split2(a.x * DS, a.y * DS, h, l);
        *(uint32_t*)(pHi + j * 144 + kp * 4) = h;
        *(uint32_t*)(pLo + j * 144 + kp * 4) = l;
    }
}

// SMEM layout, phase 1 (bytes)
#define P1_PHI  0
#define P1_PLO  36864
#define P1_FHI  73728                  // PhiT half: 128 j x 272 B
#define P1_FLO  108544
#define P1_VHI  143360                 // VT: 72 e x 272 B
#define P1_VLO  162944
#define P1_SMEM 182528

// ---------------------------------------------------------------------------
// Phase 1: keys -> g_ctxT
// ---------------------------------------------------------------------------
__global__ __launch_bounds__(256, 1) void phase1(
    const float* __restrict__ K, const float* __restrict__ V, const float* __restrict__ P)
{
    extern __shared__ char sm[];
    const int tid = threadIdx.x, w = tid >> 5, lane = tid & 31;
    const int g = lane >> 2, t4 = lane & 3;
    const int head = blockIdx.x, split = blockIdx.y;
    char* pHi = sm + P1_PHI; char* pLo = sm + P1_PLO;
    char* fHi = sm + P1_FHI; char* fLo = sm + P1_FLO;
    char* vHi = sm + P1_VHI; char* vLo = sm + P1_VLO;

    stage_proj(pHi, pLo, P, tid);
    // VT static rows: 64 = ones (ksum), 65..71 = zeros
    for (int i = tid; i < 8 * 136; i += 256) {
        int e = 64 + i / 136, t = i % 136;
        *(__nv_bfloat16*)(vHi + e * 272 + t * 2) = __float2bfloat16(e == 64 ? 1.0f : 0.0f);
        *(__nv_bfloat16*)(vLo + e * 272 + t * 2) = __float2bfloat16(0.0f);
    }

    float ctxC[2][9][4] = {};

    const float* Kb = K + ((size_t)head * T_LEN + (size_t)split * (T_LEN / SPLITS)) * DH;
    const float* Vb = V + ((size_t)head * T_LEN + (size_t)split * (T_LEN / SPLITS)) * DH;

    for (int tile = 0; tile < TILES; ++tile) {
        __syncthreads();   // prev tile's MMA2 done with PhiT/VT; proj staged (tile 0)
        // stage VT rows 0..63 (bf16 hi/lo), V[t][e] -> VT[e][t]
        {
            int tv = tid >> 1, e0 = (tid & 1) * 32;
            const float* vr = Vb + (size_t)(tile * TS + tv) * DH + e0;
            #pragma unroll
            for (int c = 0; c < 32; ++c) {
                float x = vr[c];
                __nv_bfloat16 h = __float2bfloat16(x);
                __nv_bfloat16 l = __float2bfloat16(x - __bfloat162float(h));
                *(__nv_bfloat16*)(vHi + (e0 + c) * 272 + tv * 2) = h;
                *(__nv_bfloat16*)(vLo + (e0 + c) * 272 + tv * 2) = l;
            }
        }
        // MMA1: dp[16 rows/warp][256] = K * projT, K frags from gmem
        float dp[32][4];
        #pragma unroll
        for (int nt = 0; nt < 32; ++nt) {
            dp[nt][0] = 0.f; dp[nt][1] = 0.f; dp[nt][2] = 0.f; dp[nt][3] = 0.f;
        }
        float ss0 = 0.f, ss1 = 0.f;
        const float* r0p = Kb + (size_t)(tile * TS + w * 16 + g) * DH;
        const float* r1p = r0p + 8 * DH;
        for (int s = 0; s < 4; ++s) {
            float2 a00 = *(const float2*)(r0p + s * 16 + 2 * t4);
            float2 a01 = *(const float2*)(r0p + s * 16 + 2 * t4 + 8);
            float2 a10 = *(const float2*)(r1p + s * 16 + 2 * t4);
            float2 a11 = *(const float2*)(r1p + s * 16 + 2 * t4 + 8);
            ss0 += a00.x * a00.x + a00.y * a00.y + a01.x * a01.x + a01.y * a01.y;
            ss1 += a10.x * a10.x + a10.y * a10.y + a11.x * a11.x + a11.y * a11.y;
            uint32_t aH[4], aL[4];
            split2(a00.x, a00.y, aH[0], aL[0]);
            split2(a10.x, a10.y, aH[1], aL[1]);
            split2(a01.x, a01.y, aH[2], aL[2]);
            split2(a11.x, a11.y, aH[3], aL[3]);
            const char* bh = pHi + (s * 16 + 2 * t4) * 2;
            const char* bl = pLo + (s * 16 + 2 * t4) * 2;
            #pragma unroll
            for (int nt = 0; nt < 32; ++nt) {
                int jr = (nt * 8 + g) * 144;
                mma3(dp[nt], aH, aL,
                     *(const uint32_t*)(bh + jr), *(const uint32_t*)(bh + jr + 16),
                     *(const uint32_t*)(bl + jr), *(const uint32_t*)(bl + jr + 16));
            }
        }
        // dn (row sum of squares across t4 group)
        ss0 += __shfl_xor_sync(0xffffffffu, ss0, 1);
        ss0 += __shfl_xor_sync(0xffffffffu, ss0, 2);
        ss1 += __shfl_xor_sync(0xffffffffu, ss1, 1);
        ss1 += __shfl_xor_sync(0xffffffffu, ss1, 2);
        // rowmax over full 256 cols
        float m0 = -1e30f, m1 = -1e30f;
        #pragma unroll
        for (int nt = 0; nt < 32; ++nt) {
            m0 = fmaxf(m0, fmaxf(dp[nt][0], dp[nt][1]));
            m1 = fmaxf(m1, fmaxf(dp[nt][2], dp[nt][3]));
        }
        m0 = fmaxf(m0, __shfl_xor_sync(0xffffffffu, m0, 1));
        m0 = fmaxf(m0, __shfl_xor_sync(0xffffffffu, m0, 2));
        m1 = fmaxf(m1, __shfl_xor_sync(0xffffffffu, m1, 1));
        m1 = fmaxf(m1, __shfl_xor_sync(0xffffffffu, m1, 2));
        const float off0 = 0.5f * DS * DS * ss0 + m0;
        const float off1 = 0.5f * DS * DS * ss1 + m1;

        const int tok0 = w * 16 + g, tok1 = tok0 + 8;
        // jb1 (nt 16..31): phi -> regs
        uint32_t ph1[16][4];
        #pragma unroll
        for (int nt = 0; nt < 16; ++nt) {
            float p00 = fexp(dp[nt + 16][0] - off0), p01 = fexp(dp[nt + 16][1] - off0);
            float p10 = fexp(dp[nt + 16][2] - off1), p11 = fexp(dp[nt + 16][3] - off1);
            split2(p00, p01, ph1[nt][0], ph1[nt][2]);
            split2(p10, p11, ph1[nt][1], ph1[nt][3]);
        }
        // jb0 (nt 0..15): phi -> PhiT smem [j][t]
        #pragma unroll
        for (int nt = 0; nt < 16; ++nt) {
            float p00 = fexp(dp[nt][0] - off0), p01 = fexp(dp[nt][1] - off0);
            float p10 = fexp(dp[nt][2] - off1), p11 = fexp(dp[nt][3] - off1);
            uint32_t h0, l0, h1, l1;
            split2(p00, p01, h0, l0);
            split2(p10, p11, h1, l1);
            int j = (nt * 8 + 2 * t4) * 272;
            *(uint16_t*)(fHi + j + tok0 * 2)       = (uint16_t)h0;
            *(uint16_t*)(fHi + j + 272 + tok0 * 2) = (uint16_t)(h0 >> 16);
            *(uint16_t*)(fLo + j + tok0 * 2)       = (uint16_t)l0;
            *(uint16_t*)(fLo + j + 272 + tok0 * 2) = (uint16_t)(l0 >> 16);
            *(uint16_t*)(fHi + j + tok1 * 2)       = (uint16_t)h1;
            *(uint16_t*)(fHi + j + 272 + tok1 * 2) = (uint16_t)(h1 >> 16);
            *(uint16_t*)(fLo + j + tok1 * 2)       = (uint16_t)l1;
            *(uint16_t*)(fLo + j + 272 + tok1 * 2) = (uint16_t)(l1 >> 16);
        }
        __syncthreads();
        // MMA2 jb0: ctx[j 0..127][e 0..71] += PhiT * VT
        #pragma unroll 1
        for (int ks = 0; ks < 8; ++ks) {
            int kofs = (ks * 16 + 2 * t4) * 2;
            int jr = (w * 16 + g) * 272;
            uint32_t aH[4], aL[4];
            aH[0] = *(const uint32_t*)(fHi + jr + kofs);
            aH[1] = *(const uint32_t*)(fHi + jr + 8 * 272 + kofs);
            aH[2] = *(const uint32_t*)(fHi + jr + kofs + 16);
            aH[3] = *(const uint32_t*)(fHi + jr + 8 * 272 + kofs + 16);
            aL[0] = *(const uint32_t*)(fLo + jr + kofs);
            aL[1] = *(const uint32_t*)(fLo + jr + 8 * 272 + kofs);
            aL[2] = *(const uint32_t*)(fLo + jr + kofs + 16);
            aL[3] = *(const uint32_t*)(fLo + jr + 8 * 272 + kofs + 16);
            #pragma unroll
            for (int nt = 0; nt < 9; ++nt) {
                int er = (nt * 8 + g) * 272;
                mma3(ctxC[0][nt], aH, aL,
                     *(const uint32_t*)(vHi + er + kofs), *(const uint32_t*)(vHi + er + kofs + 16),
                     *(const uint32_t*)(vLo + er + kofs), *(const uint32_t*)(vLo + er + kofs + 16));
            }
        }
        __syncthreads();
        // store jb1 PhiT from regs
        #pragma unroll
        for (int nt = 0; nt < 16; ++nt) {
            int j = (nt * 8 + 2 * t4) * 272;
            *(uint16_t*)(fHi + j + tok0 * 2)       = (uint16_t)ph1[nt][0];
            *(uint16_t*)(fHi + j + 272 + tok0 * 2) = (uint16_t)(ph1[nt][0] >> 16);
            *(uint16_t*)(fLo + j + tok0 * 2)       = (uint16_t)ph1[nt][2];
            *(uint16_t*)(fLo + j + 272 + tok0 * 2) = (uint16_t)(ph1[nt][2] >> 16);
            *(uint16_t*)(fHi + j + tok1 * 2)       = (uint16_t)ph1[nt][1];
            *(uint16_t*)(fHi + j + 272 + tok1 * 2) = (uint16_t)(ph1[nt][1] >> 16);
            *(uint16_t*)(fLo + j + tok1 * 2)       = (uint16_t)ph1[nt][3];
            *(uint16_t*)(fLo + j + 272 + tok1 * 2) = (uint16_t)(ph1[nt][3] >> 16);
        }
        __syncthreads();
        // MMA2 jb1
        #pragma unroll 1
        for (int ks = 0; ks < 8; ++ks) {
            int kofs = (ks * 16 + 2 * t4) * 2;
            int jr = (w * 16 + g) * 272;
            uint32_t aH[4], aL[4];
            aH[0] = *(const uint32_t*)(fHi + jr + kofs);
            aH[1] = *(const uint32_t*)(fHi + jr + 8 * 272 + kofs);
            aH[2] = *(const uint32_t*)(fHi + jr + kofs + 16);
            aH[3] = *(const uint32_t*)(fHi + jr + 8 * 272 + kofs + 16);
            aL[0] = *(const uint32_t*)(fLo + jr + kofs);
            aL[1] = *(const uint32_t*)(fLo + jr + 8 * 272 + kofs);
            aL[2] = *(const uint32_t*)(fLo + jr + kofs + 16);
            aL[3] = *(const uint32_t*)(fLo + jr + 8 * 272 + kofs + 16);
            #pragma unroll
            for (int nt = 0; nt < 9; ++nt) {
                int er = (nt * 8 + g) * 272;
                mma3(ctxC[1][nt], aH, aL,
                     *(const uint32_t*)(vHi + er + kofs), *(const uint32_t*)(vHi + er + kofs + 16),
                     *(const uint32_t*)(vLo + er + kofs), *(const uint32_t*)(vLo + er + kofs + 16));
            }
        }
    }
    // accumulate ctx into global
    float* cd = g_ctxT + (size_t)head * 65 * NF;
    #pragma unroll
    for (int jb = 0; jb < 2; ++jb) {
        int j0 = jb * 128 + w * 16 + g;
        #pragma unroll
        for (int nt = 0; nt < 9; ++nt) {
            int e = nt * 8 + 2 * t4;
            if (e < 65) {
                atomicAdd(cd + e * NF + j0,     ctxC[jb][nt][0]);
                atomicAdd(cd + e * NF + j0 + 8, ctxC[jb][nt][2]);
            }
            if (e + 1 < 65) {
                atomicAdd(cd + (e + 1) * NF + j0,     ctxC[jb][nt][1]);
                atomicAdd(cd + (e + 1) * NF + j0 + 8, ctxC[jb][nt][3]);
            }
        }
    }
}

// SMEM layout, phase 2
#define P2_PHI  0
#define P2_PLO  36864
#define P2_CHI  73728                 // ctx: 72 rows x 528 B
#define P2_CLO  111744
#define P2_SMEM 149760

// ---------------------------------------------------------------------------
// Phase 2: queries -> out
// ---------------------------------------------------------------------------
__global__ __launch_bounds__(256, 1) void phase2(
    const float* __restrict__ Q, const float* __restrict__ P, float* __restrict__ O)
{
    extern __shared__ char sm[];
    const int tid = threadIdx.x, w = tid >> 5, lane = tid & 31;
    const int g = lane >> 2, t4 = lane & 3;
    const int head = blockIdx.x, split = blockIdx.y;
    char* pHi = sm + P2_PHI; char* pLo = sm + P2_PLO;
    char* cHi = sm + P2_CHI; char* cLo = sm + P2_CLO;

    stage_proj(pHi, pLo, P, tid);
    // stage ctx (rows 0..64) hi/lo; rows 65..71 zero
    {
        const float* cg = g_ctxT + (size_t)head * 65 * NF;
        for (int it = tid; it < 65 * 128; it += 256) {
            int row = it >> 7, jp = it & 127;
            float2 a = *(const float2*)(cg + row * 256 + jp * 2);
            uint32_t h, l;
            split2(a.x, a.y, h, l);
            *(uint32_t*)(cHi + row * 528 + jp * 4) = h;
            *(uint32_t*)(cLo + row * 528 + jp * 4) = l;
        }
        for (int it = tid; it < 7 * 132; it += 256) {
            int row = 65 + it / 132, jp = it % 132;
            *(uint32_t*)(cHi + row * 528 + jp * 4) = 0u;
            *(uint32_t*)(cLo + row * 528 + jp * 4) = 0u;
        }
    }
    __syncthreads();

    const float* Qb = Q + ((size_t)head * T_LEN + (size_t)split * (T_LEN / SPLITS)) * DH;
    float*       Ob = O + ((size_t)head * T_LEN + (size_t)split * (T_LEN / SPLITS)) * DH;

    for (int tile = 0; tile < TILES; ++tile) {
        // MMA1: dp = Q * projT
        float dp[32][4];
        #pragma unroll
        for (int nt = 0; nt < 32; ++nt) {
            dp[nt][0] = 0.f; dp[nt][1] = 0.f; dp[nt][2] = 0.f; dp[nt][3] = 0.f;
        }
        const float* r0p = Qb + (size_t)(tile * TS + w * 16 + g) * DH;
        const float* r1p = r0p + 8 * DH;
        for (int s = 0; s < 4; ++s) {
            float2 a00 = *(const float2*)(r0p + s * 16 + 2 * t4);
            float2 a01 = *(const float2*)(r0p + s * 16 + 2 * t4 + 8);
            float2 a10 = *(const float2*)(r1p + s * 16 + 2 * t4);
            float2 a11 = *(const float2*)(r1p + s * 16 + 2 * t4 + 8);
            uint32_t aH[4], aL[4];
            split2(a00.x, a00.y, aH[0], aL[0]);
            split2(a10.x, a10.y, aH[1], aL[1]);
            split2(a01.x, a01.y, aH[2], aL[2]);
            split2(a11.x, a11.y, aH[3], aL[3]);
            const char* bh = pHi + (s * 16 + 2 * t4) * 2;
            const char* bl = pLo + (s * 16 + 2 * t4) * 2;
            #pragma unroll
            for (int nt = 0; nt < 32; ++nt) {
                int jr = (nt * 8 + g) * 144;
                mma3(dp[nt], aH, aL,
                     *(const uint32_t*)(bh + jr), *(const uint32_t*)(bh + jr + 16),
                     *(const uint32_t*)(bl + jr), *(const uint32_t*)(bl + jr + 16));
            }
        }
        // psi = exp(dp) (global max cancels for queries); MMA3: out = psi * ctxT
        float outC[9][4] = {};
        #pragma unroll
        for (int ks = 0; ks < 16; ++ks) {
            float e00 = fexp(dp[2 * ks][0]),     e01 = fexp(dp[2 * ks][1]);
            float e02 = fexp(dp[2 * ks][2]),     e03 = fexp(dp[2 * ks][3]);
            float e10 = fexp(dp[2 * ks + 1][0]), e11 = fexp(dp[2 * ks + 1][1]);
            float e12 = fexp(dp[2 * ks + 1][2]), e13 = fexp(dp[2 * ks + 1][3]);
            uint32_t aH[4], aL[4];
            split2(e00, e01, aH[0], aL[0]);
            split2(e02, e03, aH[1], aL[1]);
            split2(e10, e11, aH[2], aL[2]);
            split2(e12, e13, aH[3], aL[3]);
            int kofs = (ks * 16 + 2 * t4) * 2;
            #pragma unroll
            for (int nt = 0; nt < 9; ++nt) {
                int er = (nt * 8 + g) * 528;
                mma3(outC[nt], aH, aL,
                     *(const uint32_t*)(cHi + er + kofs), *(const uint32_t*)(cHi + er + kofs + 16),
                     *(const uint32_t*)(cLo + er + kofs), *(const uint32_t*)(cLo + er + kofs + 16));
            }
        }
        // divide by denominator (col e=64 lives in ntile 8, lane t4==0) and store
        float den0 = __shfl_sync(0xffffffffu, outC[8][0], lane & ~3);
        float den1 = __shfl_sync(0xffffffffu, outC[8][2], lane & ~3);
        float i0 = 1.0f / den0, i1 = 1.0f / den1;
        float* Or = Ob + (size_t)(tile * TS + w * 16 + g) * DH;
        #pragma unroll
        for (int nt = 0; nt < 8; ++nt) {
            float2 o0 = {outC[nt][0] * i0, outC[nt][1] * i0};
            float2 o1 = {outC[nt][2] * i1, outC[nt][3] * i1};
            *(float2*)(Or + nt * 8 + 2 * t4) = o0;
            *(float2*)(Or + 8 * DH + nt * 8 + 2 * t4) = o1;
        }
    }
}

extern "C" void kernel_launch(void* const* d_in, const int* in_sizes, int n_in,
                              void* d_out, int out_size) {
    const float* q    = (const float*)d_in[0];
    const float* k    = (const float*)d_in[1];
    const float* v    = (const float*)d_in[2];
    const float* proj = (const float*)d_in[3];
    float* out = (float*)d_out;

    cudaFuncSetAttribute(phase1, cudaFuncAttributeMaxDynamicSharedMemorySize, P1_SMEM);
    cudaFuncSetAttribute(phase2, cudaFuncAttributeMaxDynamicSharedMemorySize, P2_SMEM);

    zero_scratch<<<256, 256>>>();
    phase1<<<dim3(NHEADS, SPLITS), 256, P1_SMEM>>>(k, v, proj);
    phase2<<<dim3(NHEADS, SPLITS), 256, P2_SMEM>>>(q, proj, out);
}